// round 9
// baseline (speedup 1.0000x reference)
#include <cuda_runtime.h>
#include <cuda_fp16.h>
#include <math.h>
#include <stdint.h>

#define N_BATCH 4
#define C_DIM   256
#define P_DIM   4096
#define HB      0.5f
#define EPS     1e-5f
#define LOG2E   1.4426950408889634f

// ---------------- scratch ----------------------------------------------------
__device__ float  g_mu[C_DIM];
__device__ __half g_xh[(size_t)N_BATCH * C_DIM * P_DIM];   // [n][c][p] fp16 normalized
__device__ __half g_yh[(size_t)N_BATCH * C_DIM * P_DIM];
__device__ __half g_cosh[(size_t)N_BATCH * P_DIM * P_DIM]; // 128 MB
#define R_CHUNK 32
#define N_RCH   (P_DIM / R_CHUNK)                          // 128 row-groups per batch
__device__ float  g_colM[(size_t)N_BATCH * N_RCH * P_DIM]; // 8 MB partial col maxes of t
__device__ float  g_cxpart[N_BATCH * 8];

__device__ __forceinline__ uint32_t smem_u32(const void* p) {
    uint32_t a;
    asm("{ .reg .u64 t; cvta.to.shared.u64 t, %1; cvt.u32.u64 %0, t; }" : "=r"(a) : "l"(p));
    return a;
}
__device__ __forceinline__ void h8_to_f(uint4 u, float* f) {
    __half2* h = (__half2*)&u;
    #pragma unroll
    for (int j = 0; j < 4; j++) {
        float2 p = __half22float2(h[j]);
        f[2 * j] = p.x; f[2 * j + 1] = p.y;
    }
}
__device__ __forceinline__ void cpasync16(uint32_t smaddr, const void* gptr) {
    asm volatile("cp.async.cg.shared.global [%0], [%1], 16;" :: "r"(smaddr), "l"(gptr));
}

// ---------------- K1: per-channel mean of y ----------------------------------
__global__ void k_mean(const float* __restrict__ y) {
    int c = blockIdx.x;
    int tid = threadIdx.x;
    float s = 0.f;
    for (int n = 0; n < N_BATCH; n++) {
        const float* base = y + ((size_t)n * C_DIM + c) * P_DIM;
        for (int p = tid; p < P_DIM; p += 256) s += base[p];
    }
    __shared__ float sm[256];
    sm[tid] = s; __syncthreads();
    for (int o = 128; o > 0; o >>= 1) {
        if (tid < o) sm[tid] += sm[tid + o];
        __syncthreads();
    }
    if (tid == 0) g_mu[c] = sm[0] * (1.f / (float)(N_BATCH * P_DIM));
}

// ---------------- K2: center + normalize -> fp16 -----------------------------
__global__ __launch_bounds__(256) void k_norm(const float* __restrict__ x,
                                              const float* __restrict__ y) {
    __shared__ float mu[C_DIM];
    int tid = threadIdx.x;
    if (tid < C_DIM) mu[tid] = g_mu[tid];
    __syncthreads();

    int idx = blockIdx.x * 256 + tid;
    int n = idx / P_DIM, p = idx % P_DIM;
    const float* xb = x + (size_t)n * C_DIM * P_DIM + p;
    const float* yb = y + (size_t)n * C_DIM * P_DIM + p;

    float sx = 0.f, sy = 0.f;
    #pragma unroll 8
    for (int c = 0; c < C_DIM; c++) {
        float m  = mu[c];
        float xv = xb[(size_t)c * P_DIM] - m;
        float yv = yb[(size_t)c * P_DIM] - m;
        sx += xv * xv;
        sy += yv * yv;
    }
    float rx = rsqrtf(sx), ry = rsqrtf(sy);

    __half* xo = g_xh + (size_t)n * C_DIM * P_DIM + p;
    __half* yo = g_yh + (size_t)n * C_DIM * P_DIM + p;
    #pragma unroll 8
    for (int c = 0; c < C_DIM; c++) {
        float m = mu[c];
        xo[(size_t)c * P_DIM] = __float2half_rn((xb[(size_t)c * P_DIM] - m) * rx);
        yo[(size_t)c * P_DIM] = __float2half_rn((yb[(size_t)c * P_DIM] - m) * ry);
    }
}

// ---------------- K3: fp16 mma GEMM, 4 warps x (64x64), cp.async 3-stage -----
#define BM 128
#define BN 128
#define BK 32
#define STG 8192      // bytes per A (or B) stage: 32 k * 128 * 2B

__device__ __forceinline__ void mma_f16(float* c, const uint32_t* a, const uint32_t* b) {
    asm volatile(
        "mma.sync.aligned.m16n8k16.row.col.f32.f16.f16.f32 "
        "{%0,%1,%2,%3},{%4,%5,%6,%7},{%8,%9},{%0,%1,%2,%3};\n"
        : "+f"(c[0]), "+f"(c[1]), "+f"(c[2]), "+f"(c[3])
        : "r"(a[0]), "r"(a[1]), "r"(a[2]), "r"(a[3]), "r"(b[0]), "r"(b[1]));
}
__device__ __forceinline__ void ldsm4t(uint32_t* r, uint32_t addr) {
    asm volatile("ldmatrix.sync.aligned.m8n8.x4.trans.shared.b16 {%0,%1,%2,%3},[%4];"
                 : "=r"(r[0]), "=r"(r[1]), "=r"(r[2]), "=r"(r[3]) : "r"(addr));
}

__global__ __launch_bounds__(128, 2) void k_gemm_h() {
    __shared__ char sm[6 * STG];    // A0 A1 A2 B0 B1 B2 = 48 KB

    int nb = blockIdx.z;
    const __half* A = g_xh + (size_t)nb * C_DIM * P_DIM;
    const __half* B = g_yh + (size_t)nb * C_DIM * P_DIM;
    __half* Cm      = g_cosh + (size_t)nb * P_DIM * P_DIM;

    int tid = threadIdx.x;
    int m0 = blockIdx.x * BM, n0 = blockIdx.y * BN;
    int warp = tid >> 5, lane = tid & 31;
    int wm = warp & 1, wn = warp >> 1;
    int g = lane >> 2, t = lane & 3;
    int lg = lane >> 3, lr = lane & 7;

    uint32_t smbase = smem_u32(sm);
    uint32_t smA[3] = { smbase, smbase + STG, smbase + 2 * STG };
    uint32_t smB[3] = { smbase + 3 * STG, smbase + 4 * STG, smbase + 5 * STG };

    // per-thread copy map: 4 x 16B for A, 4 x 16B for B per stage (128 threads)
    int lk[4], lj[4];
    uint32_t soff[4];
    #pragma unroll
    for (int v = 0; v < 4; v++) {
        int idx = v * 128 + tid;
        lk[v] = idx >> 4;
        lj[v] = idx & 15;
        soff[v] = lk[v] * 256 + ((lj[v] ^ (lk[v] & 7)) << 4);
    }

    const int NST = C_DIM / BK;    // 8

    #define ISSUE(st, sb)                                                          \
    {                                                                              \
        size_t koff_ = (size_t)(st) * BK * P_DIM;                                  \
        _Pragma("unroll")                                                          \
        for (int v = 0; v < 4; v++) {                                              \
            cpasync16(smA[sb] + soff[v], A + koff_ + (size_t)lk[v] * P_DIM + m0 + lj[v] * 8); \
            cpasync16(smB[sb] + soff[v], B + koff_ + (size_t)lk[v] * P_DIM + n0 + lj[v] * 8); \
        }                                                                          \
        asm volatile("cp.async.commit_group;");                                    \
    }

    float acc[4][8][4] = {};

    ISSUE(0, 0);
    ISSUE(1, 1);

    #pragma unroll 1
    for (int st = 0; st < NST; st++) {
        asm volatile("cp.async.wait_group 1;" ::: "memory");
        __syncthreads();
        if (st + 2 < NST) ISSUE(st + 2, (st + 2) % 3);
        int buf = st % 3;

        #pragma unroll
        for (int ks = 0; ks < BK; ks += 16) {
            uint32_t af[4][4], bf[8][2];
            int ak = ks + lr + ((lg >> 1) << 3);
            #pragma unroll
            for (int im = 0; im < 4; im++) {
                int mj = wm * 8 + im * 2 + (lg & 1);
                ldsm4t(af[im], smA[buf] + ak * 256 + ((mj ^ (ak & 7)) << 4));
            }
            int bk = ks + lr + ((lg & 1) << 3);
            #pragma unroll
            for (int jp = 0; jp < 4; jp++) {
                int njc = wn * 8 + jp * 2 + (lg >> 1);
                uint32_t r[4];
                ldsm4t(r, smB[buf] + bk * 256 + ((njc ^ (bk & 7)) << 4));
                bf[jp * 2][0] = r[0]; bf[jp * 2][1] = r[1];
                bf[jp * 2 + 1][0] = r[2]; bf[jp * 2 + 1][1] = r[3];
            }
            #pragma unroll
            for (int im = 0; im < 4; im++)
                #pragma unroll
                for (int jn = 0; jn < 8; jn++)
                    mma_f16(acc[im][jn], af[im], bf[jn]);
        }
        __syncthreads();
    }

    // fp16 epilogue
    #pragma unroll
    for (int im = 0; im < 4; im++) {
        #pragma unroll
        for (int jn = 0; jn < 8; jn++) {
            int m = m0 + wm * 64 + im * 16 + g;
            int n = n0 + wn * 64 + jn * 8 + t * 2;
            *(__half2*)&Cm[(size_t)m * P_DIM + n] =
                __floats2half2_rn(acc[im][jn][0], acc[im][jn][1]);
            *(__half2*)&Cm[(size_t)(m + 8) * P_DIM + n] =
                __floats2half2_rn(acc[im][jn][2], acc[im][jn][3]);
        }
    }
}

// ---------------- K4: fused row stats + column-max, 2 rows per iteration -----
__global__ __launch_bounds__(256) void k_rowcol() {
    int blk = blockIdx.x;              // 0 .. N*P/32-1
    int tid = threadIdx.x;
    int warp = tid >> 5, lane = tid & 31;
    int row0 = blk * R_CHUNK;

    __shared__ float redm[2][2][8];    // [parity][row-in-pair][warp]
    __shared__ float reds[2][2][8];

    float colmax[16];
    #pragma unroll
    for (int i = 0; i < 16; i++) colmax[i] = -1e30f;

    #pragma unroll 1
    for (int r = 0; r < R_CHUNK; r += 2) {
        int par = (r >> 1) & 1;
        const uint4* r4a = (const uint4*)(g_cosh + (size_t)(row0 + r) * P_DIM);
        const uint4* r4b = (const uint4*)(g_cosh + (size_t)(row0 + r + 1) * P_DIM);

        float v0[16], v1[16];
        uint4 a0 = r4a[tid], a1 = r4a[tid + 256];
        uint4 b0 = r4b[tid], b1 = r4b[tid + 256];
        h8_to_f(a0, v0); h8_to_f(a1, v0 + 8);
        h8_to_f(b0, v1); h8_to_f(b1, v1 + 8);

        float m0 = v0[0], m1 = v1[0];
        #pragma unroll
        for (int i = 1; i < 16; i++) {
            m0 = fmaxf(m0, v0[i]);
            m1 = fmaxf(m1, v1[i]);
        }
        #pragma unroll
        for (int o = 16; o > 0; o >>= 1) {
            m0 = fmaxf(m0, __shfl_xor_sync(0xffffffffu, m0, o));
            m1 = fmaxf(m1, __shfl_xor_sync(0xffffffffu, m1, o));
        }
        if (lane == 0) { redm[par][0][warp] = m0; redm[par][1][warp] = m1; }
        __syncthreads();
        m0 = redm[par][0][0]; m1 = redm[par][1][0];
        #pragma unroll
        for (int w = 1; w < 8; w++) {
            m0 = fmaxf(m0, redm[par][0][w]);
            m1 = fmaxf(m1, redm[par][1][w]);
        }

        float b2_0 = LOG2E / (HB * ((1.f - m0) + EPS));
        float b2_1 = LOG2E / (HB * ((1.f - m1) + EPS));

        float s0 = 0.f, s1 = 0.f;
        #pragma unroll
        for (int i = 0; i < 16; i++) {
            s0 += exp2f(b2_0 * (v0[i] - m0));
            s1 += exp2f(b2_1 * (v1[i] - m1));
        }
        #pragma unroll
        for (int o = 16; o > 0; o >>= 1) {
            s0 += __shfl_xor_sync(0xffffffffu, s0, o);
            s1 += __shfl_xor_sync(0xffffffffu, s1, o);
        }
        if (lane == 0) { reds[par][0][warp] = s0; reds[par][1][warp] = s1; }
        __syncthreads();
        s0 = reds[par][0][0]; s1 = reds[par][1][0];
        #pragma unroll
        for (int w = 1; w < 8; w++) {
            s0 += reds[par][0][w];
            s1 += reds[par][1][w];
        }

        float bias0 = -b2_0 * m0 - log2f(s0);
        float bias1 = -b2_1 * m1 - log2f(s1);
        #pragma unroll
        for (int i = 0; i < 16; i++) {
            colmax[i] = fmaxf(colmax[i], fmaf(b2_0, v0[i], bias0));
            colmax[i] = fmaxf(colmax[i], fmaf(b2_1, v1[i], bias1));
        }
    }

    // write partials: thread owns q = tid*8..+7 and 2048 + tid*8..+7
    float* out = g_colM + (size_t)blk * P_DIM;
    *(float4*)&out[tid * 8]            = make_float4(colmax[0], colmax[1], colmax[2], colmax[3]);
    *(float4*)&out[tid * 8 + 4]        = make_float4(colmax[4], colmax[5], colmax[6], colmax[7]);
    *(float4*)&out[2048 + tid * 8]     = make_float4(colmax[8],  colmax[9],  colmax[10], colmax[11]);
    *(float4*)&out[2048 + tid * 8 + 4] = make_float4(colmax[12], colmax[13], colmax[14], colmax[15]);
}

// ---------------- K5: finish col max, one exp2 per q, sum --------------------
__global__ __launch_bounds__(256) void k_colB() {
    int n = blockIdx.y;
    int q0 = (blockIdx.x * 256 + threadIdx.x) * 2;    // grid.x = 8
    const float* cmn = g_colM + (size_t)n * N_RCH * P_DIM;
    float M0 = -1e30f, M1 = -1e30f;
    #pragma unroll 4
    for (int pc = 0; pc < N_RCH; pc++) {
        float2 v = *(const float2*)&cmn[(size_t)pc * P_DIM + q0];
        M0 = fmaxf(M0, v.x);
        M1 = fmaxf(M1, v.y);
    }
    float s = exp2f(M0) + exp2f(M1);

    __shared__ float red[256];
    red[threadIdx.x] = s; __syncthreads();
    for (int o = 128; o > 0; o >>= 1) {
        if (threadIdx.x < o) red[threadIdx.x] += red[threadIdx.x + o];
        __syncthreads();
    }
    if (threadIdx.x == 0)
        g_cxpart[n * 8 + blockIdx.x] = red[0];
}

// ---------------- K6: final scalar loss --------------------------------------
__global__ void k_final(float* __restrict__ out) {
    if (threadIdx.x == 0) {
        float loss = 0.f;
        for (int n = 0; n < N_BATCH; n++) {
            float s = 0.f;
            for (int b = 0; b < 8; b++) s += g_cxpart[n * 8 + b];
            float cx = s * (1.f / (float)P_DIM);
            loss += -logf(cx + EPS);
        }
        out[0] = loss * (1.f / (float)N_BATCH);
    }
}

// ---------------- launch ------------------------------------------------------
extern "C" void kernel_launch(void* const* d_in, const int* in_sizes, int n_in,
                              void* d_out, int out_size) {
    const float* x = (const float*)d_in[0];
    const float* y = (const float*)d_in[1];
    float* out = (float*)d_out;

    k_mean<<<C_DIM, 256>>>(y);
    k_norm<<<(N_BATCH * P_DIM) / 256, 256>>>(x, y);

    dim3 gg(P_DIM / BM, P_DIM / BN, N_BATCH);
    k_gemm_h<<<gg, 128>>>();

    k_rowcol<<<(N_BATCH * P_DIM) / R_CHUNK, 256>>>();

    dim3 gcb(P_DIM / 512, N_BATCH);
    k_colB<<<gcb, 256>>>();

    k_final<<<1, 32>>>(out);
}

// round 10
// speedup vs baseline: 1.1675x; 1.1675x over previous
#include <cuda_runtime.h>
#include <cuda_fp16.h>
#include <math.h>
#include <stdint.h>

#define N_BATCH 4
#define C_DIM   256
#define P_DIM   4096
#define HB      0.5f
#define EPS     1e-5f
#define LOG2E   1.4426950408889634f

// ---------------- scratch ----------------------------------------------------
__device__ float  g_mu[C_DIM];
__device__ __half g_xh[(size_t)N_BATCH * C_DIM * P_DIM];   // [n][c][p] fp16 normalized
__device__ __half g_yh[(size_t)N_BATCH * C_DIM * P_DIM];
__device__ __half g_cosh[(size_t)N_BATCH * P_DIM * P_DIM]; // 128 MB
#define R_CHUNK 16
#define N_RCH   (P_DIM / R_CHUNK)                          // 256 row-groups per batch
__device__ float  g_colM[(size_t)N_BATCH * N_RCH * P_DIM]; // 16 MB partial col maxes of t
__device__ float  g_cxpart[N_BATCH * 8];

__device__ __forceinline__ uint32_t smem_u32(const void* p) {
    uint32_t a;
    asm("{ .reg .u64 t; cvta.to.shared.u64 t, %1; cvt.u32.u64 %0, t; }" : "=r"(a) : "l"(p));
    return a;
}
__device__ __forceinline__ void h8_to_f(uint4 u, float* f) {
    __half2* h = (__half2*)&u;
    #pragma unroll
    for (int j = 0; j < 4; j++) {
        float2 p = __half22float2(h[j]);
        f[2 * j] = p.x; f[2 * j + 1] = p.y;
    }
}
__device__ __forceinline__ void cpasync16(uint32_t smaddr, const void* gptr) {
    asm volatile("cp.async.cg.shared.global [%0], [%1], 16;" :: "r"(smaddr), "l"(gptr));
}

// ---------------- K1: per-channel mean of y ----------------------------------
__global__ void k_mean(const float* __restrict__ y) {
    int c = blockIdx.x;
    int tid = threadIdx.x;
    float s = 0.f;
    for (int n = 0; n < N_BATCH; n++) {
        const float* base = y + ((size_t)n * C_DIM + c) * P_DIM;
        for (int p = tid; p < P_DIM; p += 256) s += base[p];
    }
    __shared__ float sm[256];
    sm[tid] = s; __syncthreads();
    for (int o = 128; o > 0; o >>= 1) {
        if (tid < o) sm[tid] += sm[tid + o];
        __syncthreads();
    }
    if (tid == 0) g_mu[c] = sm[0] * (1.f / (float)(N_BATCH * P_DIM));
}

// ---------------- K2: center + normalize -> fp16 (channel-parallel) ---------
// Block: 256 thr = 8 channel-groups x 32 p-lanes; handles 32 p positions.
// Thread keeps its 32 centered values in registers; no second global read.
__global__ __launch_bounds__(256) void k_norm(const float* __restrict__ x,
                                              const float* __restrict__ y) {
    __shared__ float mu[C_DIM];
    __shared__ float px[8][32];
    __shared__ float py[8][32];

    int tid = threadIdx.x;
    if (tid < C_DIM) mu[tid] = g_mu[tid];

    int pl = tid & 31, cg = tid >> 5;
    int blk = blockIdx.x;                       // 0 .. N*P/32-1
    int n = blk >> 7;                           // blk / 128
    int p = ((blk & 127) << 5) + pl;            // (blk%128)*32 + pl
    __syncthreads();

    const float* xb = x + ((size_t)n * C_DIM + cg * 32) * P_DIM + p;
    const float* yb = y + ((size_t)n * C_DIM + cg * 32) * P_DIM + p;

    float xv[32], yv[32];
    float sx = 0.f, sy = 0.f;
    #pragma unroll
    for (int i = 0; i < 32; i++) {
        float m = mu[cg * 32 + i];
        float a = xb[(size_t)i * P_DIM] - m;
        float b = yb[(size_t)i * P_DIM] - m;
        xv[i] = a; yv[i] = b;
        sx += a * a; sy += b * b;
    }
    px[cg][pl] = sx;
    py[cg][pl] = sy;
    __syncthreads();

    float tx = 0.f, ty = 0.f;
    #pragma unroll
    for (int w = 0; w < 8; w++) { tx += px[w][pl]; ty += py[w][pl]; }
    float rx = rsqrtf(tx), ry = rsqrtf(ty);

    __half* xo = g_xh + ((size_t)n * C_DIM + cg * 32) * P_DIM + p;
    __half* yo = g_yh + ((size_t)n * C_DIM + cg * 32) * P_DIM + p;
    #pragma unroll
    for (int i = 0; i < 32; i++) {
        xo[(size_t)i * P_DIM] = __float2half_rn(xv[i] * rx);
        yo[(size_t)i * P_DIM] = __float2half_rn(yv[i] * ry);
    }
}

// ---------------- K3: fp16 mma GEMM, 4 warps x (64x64), cp.async 3-stage -----
#define BM 128
#define BN 128
#define BK 32
#define STG 8192      // bytes per A (or B) stage: 32 k * 128 * 2B

__device__ __forceinline__ void mma_f16(float* c, const uint32_t* a, const uint32_t* b) {
    asm volatile(
        "mma.sync.aligned.m16n8k16.row.col.f32.f16.f16.f32 "
        "{%0,%1,%2,%3},{%4,%5,%6,%7},{%8,%9},{%0,%1,%2,%3};\n"
        : "+f"(c[0]), "+f"(c[1]), "+f"(c[2]), "+f"(c[3])
        : "r"(a[0]), "r"(a[1]), "r"(a[2]), "r"(a[3]), "r"(b[0]), "r"(b[1]));
}
__device__ __forceinline__ void ldsm4t(uint32_t* r, uint32_t addr) {
    asm volatile("ldmatrix.sync.aligned.m8n8.x4.trans.shared.b16 {%0,%1,%2,%3},[%4];"
                 : "=r"(r[0]), "=r"(r[1]), "=r"(r[2]), "=r"(r[3]) : "r"(addr));
}

__global__ __launch_bounds__(128, 2) void k_gemm_h() {
    __shared__ char sm[6 * STG];    // A0 A1 A2 B0 B1 B2 = 48 KB

    int nb = blockIdx.z;
    const __half* A = g_xh + (size_t)nb * C_DIM * P_DIM;
    const __half* B = g_yh + (size_t)nb * C_DIM * P_DIM;
    __half* Cm      = g_cosh + (size_t)nb * P_DIM * P_DIM;

    int tid = threadIdx.x;
    int m0 = blockIdx.x * BM, n0 = blockIdx.y * BN;
    int warp = tid >> 5, lane = tid & 31;
    int wm = warp & 1, wn = warp >> 1;
    int g = lane >> 2, t = lane & 3;
    int lg = lane >> 3, lr = lane & 7;

    uint32_t smbase = smem_u32(sm);
    uint32_t smA[3] = { smbase, smbase + STG, smbase + 2 * STG };
    uint32_t smB[3] = { smbase + 3 * STG, smbase + 4 * STG, smbase + 5 * STG };

    int lk[4], lj[4];
    uint32_t soff[4];
    #pragma unroll
    for (int v = 0; v < 4; v++) {
        int idx = v * 128 + tid;
        lk[v] = idx >> 4;
        lj[v] = idx & 15;
        soff[v] = lk[v] * 256 + ((lj[v] ^ (lk[v] & 7)) << 4);
    }

    const int NST = C_DIM / BK;    // 8

    #define ISSUE(st, sb)                                                          \
    {                                                                              \
        size_t koff_ = (size_t)(st) * BK * P_DIM;                                  \
        _Pragma("unroll")                                                          \
        for (int v = 0; v < 4; v++) {                                              \
            cpasync16(smA[sb] + soff[v], A + koff_ + (size_t)lk[v] * P_DIM + m0 + lj[v] * 8); \
            cpasync16(smB[sb] + soff[v], B + koff_ + (size_t)lk[v] * P_DIM + n0 + lj[v] * 8); \
        }                                                                          \
        asm volatile("cp.async.commit_group;");                                    \
    }

    float acc[4][8][4] = {};

    ISSUE(0, 0);
    ISSUE(1, 1);

    #pragma unroll 1
    for (int st = 0; st < NST; st++) {
        asm volatile("cp.async.wait_group 1;" ::: "memory");
        __syncthreads();
        if (st + 2 < NST) ISSUE(st + 2, (st + 2) % 3);
        int buf = st % 3;

        #pragma unroll
        for (int ks = 0; ks < BK; ks += 16) {
            uint32_t af[4][4], bf[8][2];
            int ak = ks + lr + ((lg >> 1) << 3);
            #pragma unroll
            for (int im = 0; im < 4; im++) {
                int mj = wm * 8 + im * 2 + (lg & 1);
                ldsm4t(af[im], smA[buf] + ak * 256 + ((mj ^ (ak & 7)) << 4));
            }
            int bk = ks + lr + ((lg & 1) << 3);
            #pragma unroll
            for (int jp = 0; jp < 4; jp++) {
                int njc = wn * 8 + jp * 2 + (lg >> 1);
                uint32_t r[4];
                ldsm4t(r, smB[buf] + bk * 256 + ((njc ^ (bk & 7)) << 4));
                bf[jp * 2][0] = r[0]; bf[jp * 2][1] = r[1];
                bf[jp * 2 + 1][0] = r[2]; bf[jp * 2 + 1][1] = r[3];
            }
            #pragma unroll
            for (int im = 0; im < 4; im++)
                #pragma unroll
                for (int jn = 0; jn < 8; jn++)
                    mma_f16(acc[im][jn], af[im], bf[jn]);
        }
        __syncthreads();
    }

    // fp16 epilogue
    #pragma unroll
    for (int im = 0; im < 4; im++) {
        #pragma unroll
        for (int jn = 0; jn < 8; jn++) {
            int m = m0 + wm * 64 + im * 16 + g;
            int n = n0 + wn * 64 + jn * 8 + t * 2;
            *(__half2*)&Cm[(size_t)m * P_DIM + n] =
                __floats2half2_rn(acc[im][jn][0], acc[im][jn][1]);
            *(__half2*)&Cm[(size_t)(m + 8) * P_DIM + n] =
                __floats2half2_rn(acc[im][jn][2], acc[im][jn][3]);
        }
    }
}

// ---------------- K4: fused row stats + column-max (16 rows per block) -------
__global__ __launch_bounds__(256) void k_rowcol() {
    int blk = blockIdx.x;              // 0 .. N*P/16-1
    int tid = threadIdx.x;
    int warp = tid >> 5, lane = tid & 31;
    int row0 = blk * R_CHUNK;

    __shared__ float red[2][16];       // [parity][0..7 max | 8..15 sum]

    float colmax[16];
    #pragma unroll
    for (int i = 0; i < 16; i++) colmax[i] = -1e30f;

    #pragma unroll 1
    for (int r = 0; r < R_CHUNK; r++) {
        int row = row0 + r;
        const uint4* r4 = (const uint4*)(g_cosh + (size_t)row * P_DIM);
        float v[16];
        uint4 u0 = r4[tid], u1 = r4[tid + 256];
        h8_to_f(u0, v);
        h8_to_f(u1, v + 8);

        float m = v[0];
        #pragma unroll
        for (int i = 1; i < 16; i++) m = fmaxf(m, v[i]);
        #pragma unroll
        for (int o = 16; o > 0; o >>= 1)
            m = fmaxf(m, __shfl_xor_sync(0xffffffffu, m, o));
        int par = r & 1;
        if (lane == 0) red[par][warp] = m;
        __syncthreads();
        m = red[par][0];
        #pragma unroll
        for (int w = 1; w < 8; w++) m = fmaxf(m, red[par][w]);

        float b2 = LOG2E / (HB * ((1.f - m) + EPS));

        float s = 0.f;
        #pragma unroll
        for (int i = 0; i < 16; i++) s += exp2f(b2 * (v[i] - m));
        #pragma unroll
        for (int o = 16; o > 0; o >>= 1)
            s += __shfl_xor_sync(0xffffffffu, s, o);
        if (lane == 0) red[par][8 + warp] = s;
        __syncthreads();
        s = red[par][8];
        #pragma unroll
        for (int w = 1; w < 8; w++) s += red[par][8 + w];

        float bias = -b2 * m - log2f(s);
        #pragma unroll
        for (int i = 0; i < 16; i++)
            colmax[i] = fmaxf(colmax[i], fmaf(b2, v[i], bias));
    }

    // write partials: thread owns q = tid*8..+7 and 2048 + tid*8..+7
    float* out = g_colM + (size_t)blk * P_DIM;
    *(float4*)&out[tid * 8]            = make_float4(colmax[0], colmax[1], colmax[2], colmax[3]);
    *(float4*)&out[tid * 8 + 4]        = make_float4(colmax[4], colmax[5], colmax[6], colmax[7]);
    *(float4*)&out[2048 + tid * 8]     = make_float4(colmax[8],  colmax[9],  colmax[10], colmax[11]);
    *(float4*)&out[2048 + tid * 8 + 4] = make_float4(colmax[12], colmax[13], colmax[14], colmax[15]);
}

// ---------------- K5: finish col max, one exp2 per q, sum --------------------
__global__ __launch_bounds__(256) void k_colB() {
    int n = blockIdx.y;
    int q0 = (blockIdx.x * 256 + threadIdx.x) * 2;    // grid.x = 8
    const float* cmn = g_colM + (size_t)n * N_RCH * P_DIM;
    float M0 = -1e30f, M1 = -1e30f;
    #pragma unroll 4
    for (int pc = 0; pc < N_RCH; pc++) {
        float2 v = *(const float2*)&cmn[(size_t)pc * P_DIM + q0];
        M0 = fmaxf(M0, v.x);
        M1 = fmaxf(M1, v.y);
    }
    float s = exp2f(M0) + exp2f(M1);

    __shared__ float red[256];
    red[threadIdx.x] = s; __syncthreads();
    for (int o = 128; o > 0; o >>= 1) {
        if (threadIdx.x < o) red[threadIdx.x] += red[threadIdx.x + o];
        __syncthreads();
    }
    if (threadIdx.x == 0)
        g_cxpart[n * 8 + blockIdx.x] = red[0];
}

// ---------------- K6: final scalar loss --------------------------------------
__global__ void k_final(float* __restrict__ out) {
    if (threadIdx.x == 0) {
        float loss = 0.f;
        for (int n = 0; n < N_BATCH; n++) {
            float s = 0.f;
            for (int b = 0; b < 8; b++) s += g_cxpart[n * 8 + b];
            float cx = s * (1.f / (float)P_DIM);
            loss += -logf(cx + EPS);
        }
        out[0] = loss * (1.f / (float)N_BATCH);
    }
}

// ---------------- launch ------------------------------------------------------
extern "C" void kernel_launch(void* const* d_in, const int* in_sizes, int n_in,
                              void* d_out, int out_size) {
    const float* x = (const float*)d_in[0];
    const float* y = (const float*)d_in[1];
    float* out = (float*)d_out;

    k_mean<<<C_DIM, 256>>>(y);
    k_norm<<<(N_BATCH * P_DIM) / 32, 256>>>(x, y);

    dim3 gg(P_DIM / BM, P_DIM / BN, N_BATCH);
    k_gemm_h<<<gg, 128>>>();

    k_rowcol<<<(N_BATCH * P_DIM) / R_CHUNK, 256>>>();

    dim3 gcb(P_DIM / 512, N_BATCH);
    k_colB<<<gcb, 256>>>();

    k_final<<<1, 32>>>(out);
}